// round 1
// baseline (speedup 1.0000x reference)
#include <cuda_runtime.h>
#include <cstdint>

#define NROWS 8192
#define NCODES 8192
#define HID 256

// Scratch (device globals — no allocation allowed)
__device__ unsigned long long g_min[NROWS];
__device__ float g_hsq[NROWS];
__device__ float g_csq[NCODES];

// ---------------------------------------------------------------------------
// Init per-row argmin keys
// ---------------------------------------------------------------------------
__global__ void init_min_kernel() {
    int i = blockIdx.x * blockDim.x + threadIdx.x;
    if (i < NROWS) g_min[i] = 0xFFFFFFFFFFFFFFFFull;
}

// ---------------------------------------------------------------------------
// Squared norms: one warp per row (h rows then codebook rows)
// ---------------------------------------------------------------------------
__global__ void norms_kernel(const float* __restrict__ h,
                             const float* __restrict__ cb) {
    int warp = (blockIdx.x * blockDim.x + threadIdx.x) >> 5;
    int lane = threadIdx.x & 31;
    const float* p;
    float* outp;
    if (warp < NROWS) {
        p = h + (size_t)warp * HID;
        outp = &g_hsq[warp];
    } else {
        int r = warp - NROWS;
        if (r >= NCODES) return;
        p = cb + (size_t)r * HID;
        outp = &g_csq[r];
    }
    float s = 0.f;
#pragma unroll
    for (int i = lane; i < HID; i += 32) {
        float v = p[i];
        s = fmaf(v, v, s);
    }
#pragma unroll
    for (int o = 16; o; o >>= 1) s += __shfl_xor_sync(0xFFFFFFFFu, s, o);
    if (lane == 0) *outp = s;
}

// ---------------------------------------------------------------------------
// Main: 128x128 register-tiled fp32 GEMM + per-row argmin via atomicMin(u64)
// Block: 256 threads (16x16), 8x8 micro-tile each.
// ---------------------------------------------------------------------------
__global__ __launch_bounds__(256, 2)
void vq_argmin_kernel(const float* __restrict__ h, const float* __restrict__ cb) {
    __shared__ float As[16][132];  // As[k][m] (transposed h tile), pad to avoid conflicts
    __shared__ float Bs[16][132];  // Bs[k][n] (transposed code tile)

    const int t  = threadIdx.x;
    const int tx = t & 15;
    const int ty = t >> 4;
    const int row0 = blockIdx.y * 128;
    const int col0 = blockIdx.x * 128;

    float acc[8][8];
#pragma unroll
    for (int i = 0; i < 8; ++i)
#pragma unroll
        for (int j = 0; j < 8; ++j) acc[i][j] = 0.f;

    for (int kc = 0; kc < HID; kc += 16) {
        // Load 128x16 tiles of h and codebook (transposed into smem)
#pragma unroll
        for (int it = 0; it < 8; ++it) {
            int m = it * 16 + ty;       // 0..127
            int k = tx;                 // 0..15
            As[k][m] = h[(size_t)(row0 + m) * HID + kc + k];
            Bs[k][m] = cb[(size_t)(col0 + m) * HID + kc + k];
        }
        __syncthreads();

#pragma unroll
        for (int k = 0; k < 16; ++k) {
            float4 a0 = *(const float4*)&As[k][ty * 8];
            float4 a1 = *(const float4*)&As[k][ty * 8 + 4];
            float4 b0 = *(const float4*)&Bs[k][tx * 8];
            float4 b1 = *(const float4*)&Bs[k][tx * 8 + 4];
            float a[8] = {a0.x, a0.y, a0.z, a0.w, a1.x, a1.y, a1.z, a1.w};
            float b[8] = {b0.x, b0.y, b0.z, b0.w, b1.x, b1.y, b1.z, b1.w};
#pragma unroll
            for (int i = 0; i < 8; ++i)
#pragma unroll
                for (int j = 0; j < 8; ++j) acc[i][j] = fmaf(a[i], b[j], acc[i][j]);
        }
        __syncthreads();
    }

    // Score = fl(fl(h_sq - 2*dot) + c_sq) — mirror reference rounding structure.
    float hsq[8], csq[8];
#pragma unroll
    for (int i = 0; i < 8; ++i) hsq[i] = g_hsq[row0 + ty * 8 + i];
#pragma unroll
    for (int j = 0; j < 8; ++j) csq[j] = g_csq[col0 + tx * 8 + j];

    unsigned long long best[8];
#pragma unroll
    for (int i = 0; i < 8; ++i) {
        unsigned long long bk = 0xFFFFFFFFFFFFFFFFull;
#pragma unroll
        for (int j = 0; j < 8; ++j) {
            float m2 = __fmul_rn(2.0f, acc[i][j]);
            float tt = __fsub_rn(hsq[i], m2);
            float s  = __fadd_rn(tt, csq[j]);
            unsigned u = __float_as_uint(s);
            u = (u & 0x80000000u) ? ~u : (u | 0x80000000u);  // order-preserving map
            unsigned long long key =
                ((unsigned long long)u << 32) | (unsigned)(col0 + tx * 8 + j);
            if (key < bk) bk = key;
        }
        best[i] = bk;
    }

    // Reduce across the 16 tx lanes sharing each row group (xor<16 stays in-group)
#pragma unroll
    for (int off = 8; off; off >>= 1) {
#pragma unroll
        for (int i = 0; i < 8; ++i) {
            unsigned long long o = __shfl_xor_sync(0xFFFFFFFFu, best[i], off);
            if (o < best[i]) best[i] = o;
        }
    }
    if (tx == 0) {
#pragma unroll
        for (int i = 0; i < 8; ++i)
            atomicMin(&g_min[row0 + ty * 8 + i], best[i]);
    }
}

// ---------------------------------------------------------------------------
// Finalize: one warp per row — scatter one-hot 1.0 and compute loss.
// loss = m + 0.25*m with m = mean((h - z_q)^2), matching reference structure.
// ---------------------------------------------------------------------------
__global__ void finalize_kernel(const float* __restrict__ h,
                                const float* __restrict__ cb,
                                float* __restrict__ out) {
    int warp = (blockIdx.x * blockDim.x + threadIdx.x) >> 5;
    int lane = threadIdx.x & 31;
    if (warp >= NROWS) return;

    unsigned long long key = g_min[warp];
    unsigned idx = (unsigned)(key & 0xFFFFFFFFu);

    const float* hp = h  + (size_t)warp * HID;
    const float* cp = cb + (size_t)idx * HID;
    float s = 0.f;
#pragma unroll
    for (int i = lane; i < HID; i += 32) {
        float d = hp[i] - cp[i];
        s = fmaf(d, d, s);
    }
#pragma unroll
    for (int o = 16; o; o >>= 1) s += __shfl_xor_sync(0xFFFFFFFFu, s, o);

    if (lane == 0) {
        out[(size_t)warp * NCODES + idx] = 1.0f;
        float m = s * (1.0f / (float)HID);  // exact /256
        out[(size_t)NROWS * NCODES + warp] = __fadd_rn(m, __fmul_rn(0.25f, m));
    }
}

// ---------------------------------------------------------------------------
extern "C" void kernel_launch(void* const* d_in, const int* in_sizes, int n_in,
                              void* d_out, int out_size) {
    const float* h  = (const float*)d_in[0];   // (8192, 256)
    // d_in[1] = temperature (unused)
    const float* cb = (const float*)d_in[2];   // (8192, 256)
    float* out = (float*)d_out;                // hard (N*K) then loss (N)

    // Zero the one-hot region (268 MB)
    cudaMemsetAsync(out, 0, (size_t)NROWS * NCODES * sizeof(float));

    init_min_kernel<<<(NROWS + 255) / 256, 256>>>();

    // 16384 warps total (h rows + codebook rows), 8 warps/block
    norms_kernel<<<(NROWS + NCODES) / 8, 256>>>(h, cb);

    dim3 grid(NCODES / 128, NROWS / 128);  // (64, 64)
    vq_argmin_kernel<<<grid, 256>>>(h, cb);

    finalize_kernel<<<NROWS / 8, 256>>>(h, cb, out);
}

// round 2
// speedup vs baseline: 1.0012x; 1.0012x over previous
#include <cuda_runtime.h>
#include <cstdint>

#define NROWS 8192
#define NCODES 8192
#define HID 256

// Scratch (device globals — no allocation allowed)
__device__ unsigned long long g_min[NROWS];
__device__ float g_hsq[NROWS];
__device__ float g_csq[NCODES];

// ---------------------------------------------------------------------------
// Init per-row argmin keys
// ---------------------------------------------------------------------------
__global__ void init_min_kernel() {
    int i = blockIdx.x * blockDim.x + threadIdx.x;
    if (i < NROWS) g_min[i] = 0xFFFFFFFFFFFFFFFFull;
}

// ---------------------------------------------------------------------------
// Squared norms: one warp per row (h rows then codebook rows)
// ---------------------------------------------------------------------------
__global__ void norms_kernel(const float* __restrict__ h,
                             const float* __restrict__ cb) {
    int warp = (blockIdx.x * blockDim.x + threadIdx.x) >> 5;
    int lane = threadIdx.x & 31;
    const float* p;
    float* outp;
    if (warp < NROWS) {
        p = h + (size_t)warp * HID;
        outp = &g_hsq[warp];
    } else {
        int r = warp - NROWS;
        if (r >= NCODES) return;
        p = cb + (size_t)r * HID;
        outp = &g_csq[r];
    }
    float s = 0.f;
#pragma unroll
    for (int i = lane; i < HID; i += 32) {
        float v = p[i];
        s = fmaf(v, v, s);
    }
#pragma unroll
    for (int o = 16; o; o >>= 1) s += __shfl_xor_sync(0xFFFFFFFFu, s, o);
    if (lane == 0) *outp = s;
}

// ---------------------------------------------------------------------------
// Main: 128x128 register-tiled fp32 GEMM + per-row argmin via atomicMin(u64)
// Block: 256 threads (16x16), 8x8 micro-tile each.
// ---------------------------------------------------------------------------
__global__ __launch_bounds__(256, 2)
void vq_argmin_kernel(const float* __restrict__ h, const float* __restrict__ cb) {
    __shared__ float As[16][132];  // As[k][m] (transposed h tile), pad to avoid conflicts
    __shared__ float Bs[16][132];  // Bs[k][n] (transposed code tile)

    const int t  = threadIdx.x;
    const int tx = t & 15;
    const int ty = t >> 4;
    const int row0 = blockIdx.y * 128;
    const int col0 = blockIdx.x * 128;

    float acc[8][8];
#pragma unroll
    for (int i = 0; i < 8; ++i)
#pragma unroll
        for (int j = 0; j < 8; ++j) acc[i][j] = 0.f;

    for (int kc = 0; kc < HID; kc += 16) {
        // Load 128x16 tiles of h and codebook (transposed into smem)
#pragma unroll
        for (int it = 0; it < 8; ++it) {
            int m = it * 16 + ty;       // 0..127
            int k = tx;                 // 0..15
            As[k][m] = h[(size_t)(row0 + m) * HID + kc + k];
            Bs[k][m] = cb[(size_t)(col0 + m) * HID + kc + k];
        }
        __syncthreads();

#pragma unroll
        for (int k = 0; k < 16; ++k) {
            float4 a0 = *(const float4*)&As[k][ty * 8];
            float4 a1 = *(const float4*)&As[k][ty * 8 + 4];
            float4 b0 = *(const float4*)&Bs[k][tx * 8];
            float4 b1 = *(const float4*)&Bs[k][tx * 8 + 4];
            float a[8] = {a0.x, a0.y, a0.z, a0.w, a1.x, a1.y, a1.z, a1.w};
            float b[8] = {b0.x, b0.y, b0.z, b0.w, b1.x, b1.y, b1.z, b1.w};
#pragma unroll
            for (int i = 0; i < 8; ++i)
#pragma unroll
                for (int j = 0; j < 8; ++j) acc[i][j] = fmaf(a[i], b[j], acc[i][j]);
        }
        __syncthreads();
    }

    // Score = fl(fl(h_sq - 2*dot) + c_sq) — mirror reference rounding structure.
    float hsq[8], csq[8];
#pragma unroll
    for (int i = 0; i < 8; ++i) hsq[i] = g_hsq[row0 + ty * 8 + i];
#pragma unroll
    for (int j = 0; j < 8; ++j) csq[j] = g_csq[col0 + tx * 8 + j];

    unsigned long long best[8];
#pragma unroll
    for (int i = 0; i < 8; ++i) {
        unsigned long long bk = 0xFFFFFFFFFFFFFFFFull;
#pragma unroll
        for (int j = 0; j < 8; ++j) {
            float m2 = __fmul_rn(2.0f, acc[i][j]);
            float tt = __fsub_rn(hsq[i], m2);
            float s  = __fadd_rn(tt, csq[j]);
            unsigned u = __float_as_uint(s);
            u = (u & 0x80000000u) ? ~u : (u | 0x80000000u);  // order-preserving map
            unsigned long long key =
                ((unsigned long long)u << 32) | (unsigned)(col0 + tx * 8 + j);
            if (key < bk) bk = key;
        }
        best[i] = bk;
    }

    // Reduce across the 16 tx lanes sharing each row group (xor<16 stays in-group)
#pragma unroll
    for (int off = 8; off; off >>= 1) {
#pragma unroll
        for (int i = 0; i < 8; ++i) {
            unsigned long long o = __shfl_xor_sync(0xFFFFFFFFu, best[i], off);
            if (o < best[i]) best[i] = o;
        }
    }
    if (tx == 0) {
#pragma unroll
        for (int i = 0; i < 8; ++i)
            atomicMin(&g_min[row0 + ty * 8 + i], best[i]);
    }
}

// ---------------------------------------------------------------------------
// Finalize: one warp per row — scatter one-hot 1.0 and compute loss.
// loss = m + 0.25*m with m = mean((h - z_q)^2), matching reference structure.
// ---------------------------------------------------------------------------
__global__ void finalize_kernel(const float* __restrict__ h,
                                const float* __restrict__ cb,
                                float* __restrict__ out) {
    int warp = (blockIdx.x * blockDim.x + threadIdx.x) >> 5;
    int lane = threadIdx.x & 31;
    if (warp >= NROWS) return;

    unsigned long long key = g_min[warp];
    unsigned idx = (unsigned)(key & 0xFFFFFFFFu);

    const float* hp = h  + (size_t)warp * HID;
    const float* cp = cb + (size_t)idx * HID;
    float s = 0.f;
#pragma unroll
    for (int i = lane; i < HID; i += 32) {
        float d = hp[i] - cp[i];
        s = fmaf(d, d, s);
    }
#pragma unroll
    for (int o = 16; o; o >>= 1) s += __shfl_xor_sync(0xFFFFFFFFu, s, o);

    if (lane == 0) {
        out[(size_t)warp * NCODES + idx] = 1.0f;
        float m = s * (1.0f / (float)HID);  // exact /256
        out[(size_t)NROWS * NCODES + warp] = __fadd_rn(m, __fmul_rn(0.25f, m));
    }
}

// ---------------------------------------------------------------------------
extern "C" void kernel_launch(void* const* d_in, const int* in_sizes, int n_in,
                              void* d_out, int out_size) {
    const float* h  = (const float*)d_in[0];   // (8192, 256)
    // d_in[1] = temperature (unused)
    const float* cb = (const float*)d_in[2];   // (8192, 256)
    float* out = (float*)d_out;                // hard (N*K) then loss (N)

    // Zero the one-hot region (268 MB)
    cudaMemsetAsync(out, 0, (size_t)NROWS * NCODES * sizeof(float));

    init_min_kernel<<<(NROWS + 255) / 256, 256>>>();

    // 16384 warps total (h rows + codebook rows), 8 warps/block
    norms_kernel<<<(NROWS + NCODES) / 8, 256>>>(h, cb);

    dim3 grid(NCODES / 128, NROWS / 128);  // (64, 64)
    vq_argmin_kernel<<<grid, 256>>>(h, cb);

    finalize_kernel<<<NROWS / 8, 256>>>(h, cb, out);
}